// round 9
// baseline (speedup 1.0000x reference)
#include <cuda_runtime.h>
#include <cuda_bf16.h>

// ---------------------------------------------------------------------------
// LaplacianRegularization
//   degree = segment_sum(w, row);  ys = bf16( y * rsqrt(degree)[:,None] )
//   out = mean_e( ||ys[row] - ys[col]||_2 * w_e )
//
// Inputs (metadata order):
//   d_in[0] : edge_index  int64 OR int32 (2, E)   (dtype detected on-device)
//   d_in[1] : edge_weights float32 (E,)
//   d_in[2] : y            float32 (N, 16)
// Output: 1 float
//
// 4 launches: k_zero (+dtype probe), k_degree, k_scale (fp32->bf16 rows),
// k_main (2 lanes per edge: one uint4 = 8 bf16 components per lane).
// ---------------------------------------------------------------------------

#define MAX_NODES 131072

__device__ float    g_deg[MAX_NODES];
__device__ uint4    g_ysb[MAX_NODES * 2];   // bf16 rows: 16 x bf16 = 32B = 2 x uint4
__device__ double   g_sum;
__device__ unsigned g_flag;    // !=0 => edge_index is int32
__device__ unsigned g_count;   // finished-block ticket

__device__ __forceinline__ int load_idx(const void* ei, long long pos, bool is32) {
    if (is32) return ((const int*)ei)[pos];
    return (int)((const long long*)ei)[pos];
}

// --- K1: zero scratch; block 0 probes the index dtype -----------------------
__global__ void k_zero(const unsigned* __restrict__ words, int E, int n) {
    int i = blockIdx.x * blockDim.x + threadIdx.x;
    int n4 = (n + 3) >> 2;
    if (i < n4) ((float4*)g_deg)[i] = make_float4(0, 0, 0, 0);
    if (i == 0) { g_sum = 0.0; g_count = 0u; }

    if (blockIdx.x == 0) {
        int samples = E < 1024 ? E : 1024;
        unsigned v = 0;
        for (int s = threadIdx.x; s < samples; s += blockDim.x)
            v |= words[2 * s + 1];
        #pragma unroll
        for (int o = 16; o > 0; o >>= 1)
            v |= __shfl_xor_sync(0xFFFFFFFFu, v, o);
        __shared__ unsigned sh[8];
        int lane = threadIdx.x & 31, warp = threadIdx.x >> 5;
        if (lane == 0) sh[warp] = v;
        __syncthreads();
        if (threadIdx.x == 0) {
            unsigned r = 0;
            for (int k = 0; k < (int)(blockDim.x >> 5); k++) r |= sh[k];
            g_flag = r;
        }
    }
}

// --- K2: degree = segment_sum(w, row) ----------------------------------------
__global__ void k_degree(const void* __restrict__ ei,
                         const float* __restrict__ w, int E, int N) {
    int e = blockIdx.x * blockDim.x + threadIdx.x;
    if (e >= E) return;
    const bool is32 = (g_flag != 0u);
    int r = load_idx(ei, e, is32);
    if ((unsigned)r < (unsigned)N)
        atomicAdd(&g_deg[r], w[e]);
}

// --- K3: ys(bf16) = y * rsqrt(degree) ------------------------------------------
// One thread per half-row (8 floats -> 8 bf16 -> one uint4).
__global__ void k_scale(const float4* __restrict__ y4, int N) {
    int i = blockIdx.x * blockDim.x + threadIdx.x;   // half-row index
    if (i >= 2 * N) return;
    int node = i >> 1;
    float s = rsqrtf(g_deg[node]);
    float4 u = __ldg(y4 + 2 * i);
    float4 v = __ldg(y4 + 2 * i + 1);
    __nv_bfloat162 p0 = __float22bfloat162_rn(make_float2(u.x * s, u.y * s));
    __nv_bfloat162 p1 = __float22bfloat162_rn(make_float2(u.z * s, u.w * s));
    __nv_bfloat162 p2 = __float22bfloat162_rn(make_float2(v.x * s, v.y * s));
    __nv_bfloat162 p3 = __float22bfloat162_rn(make_float2(v.z * s, v.w * s));
    uint4 out;
    out.x = *(unsigned*)&p0; out.y = *(unsigned*)&p1;
    out.z = *(unsigned*)&p2; out.w = *(unsigned*)&p3;
    g_ysb[i] = out;
}

// --- K4: per-edge norm + reduce + finalize -------------------------------------
// 2 lanes per edge: lane pair (2e, 2e+1); each lane loads one 16B half-row of
// ys[r] and ys[c], computes 8 bf16 diffs, fp32 square-accumulates, pair-reduces.
#define EDGES_PER_BLOCK 128   // 8 warps x 16 edges

__device__ __forceinline__ float acc8(uint4 va, uint4 vb, float acc) {
    const __nv_bfloat162* a = (const __nv_bfloat162*)&va;
    const __nv_bfloat162* b = (const __nv_bfloat162*)&vb;
    #pragma unroll
    for (int k = 0; k < 4; k++) {
        float2 d = __bfloat1622float2(__hsub2(a[k], b[k]));
        acc = fmaf(d.x, d.x, acc);
        acc = fmaf(d.y, d.y, acc);
    }
    return acc;
}

__global__ void __launch_bounds__(256)
k_main(const void* __restrict__ ei,
       const float* __restrict__ w,
       float* __restrict__ out, int E, int N, int nblocks) {
    const bool is32 = (g_flag != 0u);
    const int lane  = threadIdx.x & 31;
    const int warp  = threadIdx.x >> 5;
    const int half  = lane & 1;

    long long eidx = (long long)blockIdx.x * EDGES_PER_BLOCK + warp * 16 + (lane >> 1);

    int r = 0, c = 0;
    float wgt = 0.0f;
    if (eidx < (long long)E) {
        r   = load_idx(ei, eidx, is32);
        c   = load_idx(ei, (long long)E + eidx, is32);
        wgt = __ldg(w + eidx);
        if ((unsigned)r >= (unsigned)N || (unsigned)c >= (unsigned)N) {
            r = 0; c = 0; wgt = 0.0f;   // defensive: never trap
        }
    }

    // Two independent 16B gathers per lane (1 line each; 16 rows per warp instr)
    uint4 va = g_ysb[(size_t)r * 2 + half];
    uint4 vb = g_ysb[(size_t)c * 2 + half];

    float acc = acc8(va, vb, 0.0f);
    acc += __shfl_xor_sync(0xFFFFFFFFu, acc, 1);      // pair reduce -> full norm^2

    float val = (half == 0) ? sqrtf(acc) * wgt : 0.0f;

    // warp + block reduce
    #pragma unroll
    for (int o = 16; o > 0; o >>= 1)
        val += __shfl_down_sync(0xFFFFFFFFu, val, o);

    __shared__ float s_warp[8];
    if (lane == 0) s_warp[warp] = val;
    __syncthreads();

    if (warp == 0) {
        val = (lane < (int)(blockDim.x >> 5)) ? s_warp[lane] : 0.0f;
        #pragma unroll
        for (int o = 4; o > 0; o >>= 1)
            val += __shfl_down_sync(0xFFFFFFFFu, val, o);
        if (lane == 0) {
            atomicAdd(&g_sum, (double)val);
            __threadfence();
            unsigned ticket = atomicInc(&g_count, 0xFFFFFFFFu);
            if (ticket == (unsigned)(nblocks - 1))
                *out = (float)(g_sum / (double)E);
        }
    }
}

extern "C" void kernel_launch(void* const* d_in, const int* in_sizes, int n_in,
                              void* d_out, int out_size) {
    const void*   ei  = d_in[0];
    const float*  w   = (const float*)d_in[1];
    const float4* y4  = (const float4*)d_in[2];
    float*        out = (float*)d_out;

    const int E = in_sizes[1];       // number of edges
    const int N = in_sizes[2] / 16;  // number of nodes

    const int T = 256;
    int blocksZ = ((N + 3) / 4 + T - 1) / T;
    int blocksE = (E + T - 1) / T;
    int blocksS = (2 * N + T - 1) / T;
    int blocksM = (E + EDGES_PER_BLOCK - 1) / EDGES_PER_BLOCK;

    k_zero  <<<blocksZ, T>>>((const unsigned*)ei, E, N);
    k_degree<<<blocksE, T>>>(ei, w, E, N);
    k_scale <<<blocksS, T>>>(y4, N);
    k_main  <<<blocksM, T>>>(ei, w, out, E, N, blocksM);
}